// round 3
// baseline (speedup 1.0000x reference)
#include <cuda_runtime.h>
#include <math.h>

// Problem constants (fixed shape for this problem)
#define B_   4
#define S_   2048
#define D_   1024
#define H_   16
#define DK   64
#define MSEQ 2048

// Scratch (allocation-free rule: __device__ globals)
__device__ float g_q[B_ * S_ * D_];
__device__ float g_k[B_ * S_ * D_];
__device__ float g_v[B_ * S_ * D_];
__device__ float g_att[B_ * S_ * D_];
__device__ float g_cos[MSEQ * (DK / 2)];
__device__ float g_sin[MSEQ * (DK / 2)];

// ---------------------------------------------------------------------------
// token_positions dtype guard: reference declares int64 but JAX without x64
// stores int32. Detect from word 1 of the int32 view:
//   int32 arange: w[1] == 1 ; int64 arange: w[1] == high word of elem 0 == 0.
// Then elem s lives at w[s] (int32) or w[2s] (int64 little-endian low word).
// ---------------------------------------------------------------------------
__device__ __forceinline__ int get_pos(const int* __restrict__ tp32, int s) {
    return (tp32[1] == 0) ? tp32[2 * s] : tp32[s];
}

// ---------------------------------------------------------------------------
// RoPE tables: cos/sin(pos * theta^(-2j/d_k)), computed in fp64 for accuracy.
// ---------------------------------------------------------------------------
__global__ void rope_table_kernel() {
    int i = blockIdx.x * blockDim.x + threadIdx.x;
    if (i < MSEQ * (DK / 2)) {
        int pos = i >> 5;          // row (position)
        int j   = i & 31;          // pair index
        double freq = pow(10000.0, -(double)(2 * j) / (double)DK);
        double ang  = (double)pos * freq;
        g_cos[i] = (float)cos(ang);
        g_sin[i] = (float)sin(ang);
    }
}

// ---------------------------------------------------------------------------
// SGEMM: C[M,N] = A[M,K] @ W[K,N], M=8192, N=K=1024.
// 128x128x8 tile, 256 threads, 8x8 per-thread micro-tile.
// Optional fused interleaved-RoPE epilogue (pairs within thread's 8 cols).
// ---------------------------------------------------------------------------
__global__ __launch_bounds__(256) void sgemm_kernel(
    const float* __restrict__ A, const float* __restrict__ W,
    float* __restrict__ C, const int* __restrict__ tp32, int rope)
{
    const int N = D_, K = D_;
    __shared__ float As[8][128];
    __shared__ float Bs[8][128];

    const int tid = threadIdx.x;
    const int tx = tid & 15;        // 0..15 -> col group
    const int ty = tid >> 4;        // 0..15 -> row group
    const int rowBase = blockIdx.y * 128;
    const int colBase = blockIdx.x * 128;

    const int arow = tid >> 1;          // 0..127
    const int acol = (tid & 1) * 4;     // 0 or 4
    const int brow = tid >> 5;          // 0..7
    const int bcol = (tid & 31) * 4;    // 0..124

    const float* Ap = A + (size_t)(rowBase + arow) * K + acol;
    const float* Bp = W + (size_t)brow * N + colBase + bcol;

    float acc[8][8];
#pragma unroll
    for (int i = 0; i < 8; i++)
#pragma unroll
        for (int j = 0; j < 8; j++) acc[i][j] = 0.f;

    for (int k0 = 0; k0 < K; k0 += 8) {
        float4 av = *(const float4*)Ap;
        float4 bv = *(const float4*)Bp;
        As[acol + 0][arow] = av.x;
        As[acol + 1][arow] = av.y;
        As[acol + 2][arow] = av.z;
        As[acol + 3][arow] = av.w;
        *(float4*)&Bs[brow][bcol] = bv;
        __syncthreads();

#pragma unroll
        for (int kk = 0; kk < 8; kk++) {
            float4 a0 = *(const float4*)&As[kk][ty * 8];
            float4 a1 = *(const float4*)&As[kk][ty * 8 + 4];
            float4 b0 = *(const float4*)&Bs[kk][tx * 8];
            float4 b1 = *(const float4*)&Bs[kk][tx * 8 + 4];
            float a[8] = {a0.x, a0.y, a0.z, a0.w, a1.x, a1.y, a1.z, a1.w};
            float b[8] = {b0.x, b0.y, b0.z, b0.w, b1.x, b1.y, b1.z, b1.w};
#pragma unroll
            for (int i = 0; i < 8; i++)
#pragma unroll
                for (int j = 0; j < 8; j++)
                    acc[i][j] += a[i] * b[j];
        }
        __syncthreads();
        Ap += 8;
        Bp += (size_t)8 * N;
    }

    if (rope) {
#pragma unroll
        for (int i = 0; i < 8; i++) {
            int row = rowBase + ty * 8 + i;
            int s = row & (S_ - 1);
            int pos = get_pos(tp32, s);
            const float* cb = g_cos + pos * (DK / 2);
            const float* sb = g_sin + pos * (DK / 2);
#pragma unroll
            for (int jj = 0; jj < 4; jj++) {
                int col = colBase + tx * 8 + 2 * jj;
                int pj = (col & (DK - 1)) >> 1;
                float c = cb[pj], sn = sb[pj];
                float e = acc[i][2 * jj], o = acc[i][2 * jj + 1];
                acc[i][2 * jj]     = e * c - o * sn;
                acc[i][2 * jj + 1] = o * c + e * sn;
            }
        }
    }

#pragma unroll
    for (int i = 0; i < 8; i++) {
        int row = rowBase + ty * 8 + i;
        float* Cp = C + (size_t)row * N + colBase + tx * 8;
        float4 o0 = make_float4(acc[i][0], acc[i][1], acc[i][2], acc[i][3]);
        float4 o1 = make_float4(acc[i][4], acc[i][5], acc[i][6], acc[i][7]);
        *(float4*)Cp = o0;
        *(float4*)(Cp + 4) = o1;
    }
}

// ---------------------------------------------------------------------------
// Flash attention, fp32, causal. One block per (b, h, qtile).
// BM=BN=64, d=64, 128 threads: thread grid 16(rows) x 8(cols), 4x8 tiles.
// ---------------------------------------------------------------------------
#define FA_SMEM ((3 * 64 * 65 + 64 * 64) * 4)

__global__ __launch_bounds__(128) void flash_kernel() {
    extern __shared__ float sm[];
    float* q_s = sm;                 // [64][65]
    float* k_s = sm + 64 * 65;       // [64][65]
    float* p_s = sm + 2 * 64 * 65;   // [64][65]
    float* v_s = sm + 3 * 64 * 65;   // [64][64]

    const int tid = threadIdx.x;
    const int ty = tid >> 3;   // 0..15 -> query rows ty*4..ty*4+3
    const int tx = tid & 7;    // 0..7  -> cols tx*8..tx*8+7
    const int qt = blockIdx.x; // query tile 0..31
    const int bh = blockIdx.y;
    const int b = bh >> 4;
    const int h = bh & 15;

    const float* qg = g_q + ((size_t)(b * S_) + qt * 64) * D_ + h * DK;
    for (int idx = tid; idx < 64 * 16; idx += 128) {
        int r = idx >> 4, c4 = idx & 15;
        float4 v = *(const float4*)(qg + (size_t)r * D_ + c4 * 4);
        float* dst = q_s + r * 65 + c4 * 4;
        dst[0] = v.x; dst[1] = v.y; dst[2] = v.z; dst[3] = v.w;
    }

    float m[4], l[4], acc[4][8];
#pragma unroll
    for (int i = 0; i < 4; i++) {
        m[i] = -INFINITY;
        l[i] = 0.f;
#pragma unroll
        for (int j = 0; j < 8; j++) acc[i][j] = 0.f;
    }

    for (int kt = 0; kt <= qt; kt++) {
        const float* kg = g_k + ((size_t)(b * S_) + kt * 64) * D_ + h * DK;
        const float* vg = g_v + ((size_t)(b * S_) + kt * 64) * D_ + h * DK;
        for (int idx = tid; idx < 64 * 16; idx += 128) {
            int r = idx >> 4, c4 = idx & 15;
            float4 kv = *(const float4*)(kg + (size_t)r * D_ + c4 * 4);
            float* kd = k_s + r * 65 + c4 * 4;
            kd[0] = kv.x; kd[1] = kv.y; kd[2] = kv.z; kd[3] = kv.w;
            float4 vv = *(const float4*)(vg + (size_t)r * D_ + c4 * 4);
            *(float4*)(v_s + r * 64 + c4 * 4) = vv;
        }
        __syncthreads();

        // --- GEMM1: S = Q K^T ---
        float sc[4][8];
#pragma unroll
        for (int i = 0; i < 4; i++)
#pragma unroll
            for (int j = 0; j < 8; j++) sc[i][j] = 0.f;

#pragma unroll 4
        for (int d = 0; d < 64; d++) {
            float a[4], bb[8];
#pragma unroll
            for (int i = 0; i < 4; i++) a[i] = q_s[(ty * 4 + i) * 65 + d];
#pragma unroll
            for (int j = 0; j < 8; j++) bb[j] = k_s[(tx * 8 + j) * 65 + d];
#pragma unroll
            for (int i = 0; i < 4; i++)
#pragma unroll
                for (int j = 0; j < 8; j++)
                    sc[i][j] += a[i] * bb[j];
        }

        const float scale = 0.125f;  // 1/sqrt(64)
        if (kt == qt) {
#pragma unroll
            for (int i = 0; i < 4; i++) {
                int rg = ty * 4 + i;
#pragma unroll
                for (int j = 0; j < 8; j++) {
                    int cg = tx * 8 + j;
                    sc[i][j] = (cg <= rg) ? sc[i][j] * scale : -INFINITY;
                }
            }
        } else {
#pragma unroll
            for (int i = 0; i < 4; i++)
#pragma unroll
                for (int j = 0; j < 8; j++) sc[i][j] *= scale;
        }

        // --- online softmax ---
#pragma unroll
        for (int i = 0; i < 4; i++) {
            float tm = sc[i][0];
#pragma unroll
            for (int j = 1; j < 8; j++) tm = fmaxf(tm, sc[i][j]);
            tm = fmaxf(tm, __shfl_xor_sync(0xffffffffu, tm, 1));
            tm = fmaxf(tm, __shfl_xor_sync(0xffffffffu, tm, 2));
            tm = fmaxf(tm, __shfl_xor_sync(0xffffffffu, tm, 4));
            float newm = fmaxf(m[i], tm);
            float corr = __expf(m[i] - newm);
            float ps = 0.f;
#pragma unroll
            for (int j = 0; j < 8; j++) {
                float p = __expf(sc[i][j] - newm);
                p_s[(ty * 4 + i) * 65 + tx * 8 + j] = p;
                ps += p;
            }
            ps += __shfl_xor_sync(0xffffffffu, ps, 1);
            ps += __shfl_xor_sync(0xffffffffu, ps, 2);
            ps += __shfl_xor_sync(0xffffffffu, ps, 4);
            l[i] = l[i] * corr + ps;
            m[i] = newm;
#pragma unroll
            for (int j = 0; j < 8; j++) acc[i][j] *= corr;
        }
        __syncthreads();

        // --- GEMM2: O += P V ---
#pragma unroll 4
        for (int k = 0; k < 64; k++) {
            float a[4];
#pragma unroll
            for (int i = 0; i < 4; i++) a[i] = p_s[(ty * 4 + i) * 65 + k];
            float4 b0 = *(const float4*)(v_s + k * 64 + tx * 8);
            float4 b1 = *(const float4*)(v_s + k * 64 + tx * 8 + 4);
            float bb[8] = {b0.x, b0.y, b0.z, b0.w, b1.x, b1.y, b1.z, b1.w};
#pragma unroll
            for (int i = 0; i < 4; i++)
#pragma unroll
                for (int j = 0; j < 8; j++)
                    acc[i][j] += a[i] * bb[j];
        }
        __syncthreads();
    }

    // epilogue: O /= l, write out
    float* og = g_att + ((size_t)(b * S_) + qt * 64) * D_ + h * DK;
#pragma unroll
    for (int i = 0; i < 4; i++) {
        float inv = 1.f / l[i];
        int r = ty * 4 + i;
        float4 o0 = make_float4(acc[i][0] * inv, acc[i][1] * inv,
                                acc[i][2] * inv, acc[i][3] * inv);
        float4 o1 = make_float4(acc[i][4] * inv, acc[i][5] * inv,
                                acc[i][6] * inv, acc[i][7] * inv);
        *(float4*)(og + (size_t)r * D_ + tx * 8) = o0;
        *(float4*)(og + (size_t)r * D_ + tx * 8 + 4) = o1;
    }
}

// ---------------------------------------------------------------------------
// Launcher
// ---------------------------------------------------------------------------
extern "C" void kernel_launch(void* const* d_in, const int* in_sizes, int n_in,
                              void* d_out, int out_size)
{
    const float* x      = (const float*)d_in[0];
    const float* wq     = (const float*)d_in[1];
    const float* wk     = (const float*)d_in[2];
    const float* wv     = (const float*)d_in[3];
    const float* wo     = (const float*)d_in[4];
    const int*   tp32   = (const int*)d_in[5];   // int32 or int64 view, detected on device

    (void)in_sizes; (void)n_in; (void)out_size;

    cudaFuncSetAttribute(flash_kernel,
                         cudaFuncAttributeMaxDynamicSharedMemorySize, FA_SMEM);

    void *pq, *pk, *pv, *pa;
    cudaGetSymbolAddress(&pq, g_q);
    cudaGetSymbolAddress(&pk, g_k);
    cudaGetSymbolAddress(&pv, g_v);
    cudaGetSymbolAddress(&pa, g_att);

    // 1. RoPE tables
    rope_table_kernel<<<(MSEQ * (DK / 2) + 255) / 256, 256>>>();

    // 2. QKV projections (RoPE fused for Q, K)
    dim3 gg(D_ / 128, (B_ * S_) / 128);
    sgemm_kernel<<<gg, 256>>>(x, wq, (float*)pq, tp32, 1);
    sgemm_kernel<<<gg, 256>>>(x, wk, (float*)pk, tp32, 1);
    sgemm_kernel<<<gg, 256>>>(x, wv, (float*)pv, tp32, 0);

    // 3. Causal flash attention
    dim3 gf(S_ / 64, B_ * H_);
    flash_kernel<<<gf, 128, FA_SMEM>>>();

    // 4. Output projection
    sgemm_kernel<<<gg, 256>>>((const float*)pa, wo, (float*)d_out, tp32, 0);
}

// round 6
// speedup vs baseline: 1.4946x; 1.4946x over previous
#include <cuda_runtime.h>
#include <cuda_bf16.h>
#include <math.h>
#include <stdint.h>

// Problem constants
#define B_   4
#define S_   2048
#define D_   1024
#define H_   16
#define DK   64
#define MSEQ 2048
#define M_   (B_ * S_)   // 8192

// ---------------------------------------------------------------------------
// Scratch (__device__ globals; no allocations allowed)
// ---------------------------------------------------------------------------
__device__ float g_q[M_ * D_];
__device__ float g_k[M_ * D_];
__device__ float g_v[M_ * D_];
__device__ float g_att[M_ * D_];
__device__ float g_cos[MSEQ * (DK / 2)];
__device__ float g_sin[MSEQ * (DK / 2)];

__device__ __align__(16) __nv_bfloat16 g_xh[M_ * D_];
__device__ __align__(16) __nv_bfloat16 g_xl[M_ * D_];
__device__ __align__(16) __nv_bfloat16 g_ath[M_ * D_];
__device__ __align__(16) __nv_bfloat16 g_atl[M_ * D_];
// transposed+split weights: [N=1024][K=1024] (k contiguous)
__device__ __align__(16) __nv_bfloat16 g_wqh[D_ * D_];
__device__ __align__(16) __nv_bfloat16 g_wql[D_ * D_];
__device__ __align__(16) __nv_bfloat16 g_wkh[D_ * D_];
__device__ __align__(16) __nv_bfloat16 g_wkl[D_ * D_];
__device__ __align__(16) __nv_bfloat16 g_wvh[D_ * D_];
__device__ __align__(16) __nv_bfloat16 g_wvl[D_ * D_];
__device__ __align__(16) __nv_bfloat16 g_woh[D_ * D_];
__device__ __align__(16) __nv_bfloat16 g_wol[D_ * D_];

// ---------------------------------------------------------------------------
// PTX helpers (sm_80+ features only — NO tcgen05, harness targets sm_103 plain)
// ---------------------------------------------------------------------------
__device__ __forceinline__ uint32_t smem_to_u32(const void* p) {
    uint32_t a;
    asm("{ .reg .u64 t; cvta.to.shared.u64 t, %1; cvt.u32.u64 %0, t; }"
        : "=r"(a) : "l"(p));
    return a;
}
#define CP_ASYNC16(dst_u32, src_ptr) \
    asm volatile("cp.async.cg.shared.global [%0], [%1], 16;" \
                 :: "r"(dst_u32), "l"(src_ptr))
#define CP_COMMIT() asm volatile("cp.async.commit_group;" ::: "memory")
#define LDMATRIX_X4(r0, r1, r2, r3, addr) \
    asm volatile("ldmatrix.sync.aligned.m8n8.x4.shared.b16 {%0,%1,%2,%3}, [%4];" \
                 : "=r"(r0), "=r"(r1), "=r"(r2), "=r"(r3) : "r"(addr))
#define MMA_BF16(c, a, b0, b1) \
    asm volatile("mma.sync.aligned.m16n8k16.row.col.f32.bf16.bf16.f32 " \
                 "{%0,%1,%2,%3}, {%4,%5,%6,%7}, {%8,%9}, {%0,%1,%2,%3};" \
                 : "+f"((c)[0]), "+f"((c)[1]), "+f"((c)[2]), "+f"((c)[3]) \
                 : "r"((a)[0]), "r"((a)[1]), "r"((a)[2]), "r"((a)[3]), \
                   "r"(b0), "r"(b1))

// ---------------------------------------------------------------------------
// token_positions dtype guard (int32 vs int64 little-endian)
// ---------------------------------------------------------------------------
__device__ __forceinline__ int get_pos(const int* __restrict__ tp32, int s) {
    return (tp32[1] == 0) ? tp32[2 * s] : tp32[s];
}

// ---------------------------------------------------------------------------
// RoPE tables
// ---------------------------------------------------------------------------
__global__ void rope_table_kernel() {
    int i = blockIdx.x * blockDim.x + threadIdx.x;
    if (i < MSEQ * (DK / 2)) {
        int pos = i >> 5;
        int j   = i & 31;
        double freq = pow(10000.0, -(double)(2 * j) / (double)DK);
        double ang  = (double)pos * freq;
        g_cos[i] = (float)cos(ang);
        g_sin[i] = (float)sin(ang);
    }
}

// ---------------------------------------------------------------------------
// Elementwise fp32 -> (bf16 hi, bf16 lo) split
// ---------------------------------------------------------------------------
__global__ void split_kernel(const float* __restrict__ in,
                             __nv_bfloat16* __restrict__ hi,
                             __nv_bfloat16* __restrict__ lo, int n)
{
    int i = blockIdx.x * blockDim.x + threadIdx.x;
    if (i < n) {
        float v = in[i];
        __nv_bfloat16 h = __float2bfloat16(v);
        hi[i] = h;
        lo[i] = __float2bfloat16(v - __bfloat162float(h));
    }
}

// ---------------------------------------------------------------------------
// Weight transpose + split: W[K][N] fp32 -> th/tl[N][K] bf16
// ---------------------------------------------------------------------------
__global__ void wsplit_kernel(const float* __restrict__ W,
                              __nv_bfloat16* __restrict__ th,
                              __nv_bfloat16* __restrict__ tl)
{
    __shared__ float t[32][33];
    int bx = blockIdx.x * 32;  // n block
    int by = blockIdx.y * 32;  // k block
    int tx = threadIdx.x, ty = threadIdx.y;
    for (int i = ty; i < 32; i += 8)
        t[i][tx] = W[(size_t)(by + i) * D_ + bx + tx];
    __syncthreads();
    for (int i = ty; i < 32; i += 8) {
        float v = t[tx][i];  // = W[by+tx][bx+i]
        __nv_bfloat16 h = __float2bfloat16(v);
        size_t o = (size_t)(bx + i) * D_ + by + tx;
        th[o] = h;
        tl[o] = __float2bfloat16(v - __bfloat162float(h));
    }
}

// ---------------------------------------------------------------------------
// HMMA split-bf16 GEMM: C[M_,1024] = A @ W
//   A as hi/lo bf16 [M_,1024] row-major; W as Bh/Bl [1024(N),1024(K)] bf16.
//   C = Ah*Bh + Ah*Bl + Al*Bh (fp32 accum) — ~1e-5 relative accuracy.
// Tile 128x128, 8 warps (2m x 4n, 64x32 each), K-chunk 32, double-buffered
// cp.async stages, 80B-padded smem rows (conflict-free ldmatrix).
// Optional fused interleaved RoPE in epilogue.
// ---------------------------------------------------------------------------
#define KCH      32
#define ROW_STR  80                       // 64B data + 16B pad
#define TILE_B   (128 * ROW_STR)          // 10240
#define STAGE_B  (4 * TILE_B)             // Ah, Al, Bh, Bl
#define GEMM_SMEM (2 * STAGE_B)           // 81920

__global__ __launch_bounds__(256) void hmma_gemm_kernel(
    const __nv_bfloat16* __restrict__ Ah, const __nv_bfloat16* __restrict__ Al,
    const __nv_bfloat16* __restrict__ Bh, const __nv_bfloat16* __restrict__ Bl,
    float* __restrict__ C, const int* __restrict__ tp32, int rope)
{
    extern __shared__ char smem[];
    const uint32_t sbase = smem_to_u32(smem);

    const int tid = threadIdx.x;
    const int w = tid >> 5;
    const int l = tid & 31;
    const int n0 = blockIdx.x * 128;
    const int m0 = blockIdx.y * 128;
    const int warp_m = w >> 2;   // 0..1
    const int warp_n = w & 3;    // 0..3

    float acc[4][4][4];
#pragma unroll
    for (int mt = 0; mt < 4; mt++)
#pragma unroll
        for (int nt = 0; nt < 4; nt++)
#pragma unroll
            for (int r = 0; r < 4; r++) acc[mt][nt][r] = 0.f;

    // ldmatrix lane -> (row, k-chunk) mapping
    const int mat = l >> 3, lr = l & 7;
    // A x4: matrices (m0-7,k0-7),(m8-15,k0-7),(m0-7,k8-15),(m8-15,k8-15)
    const int a_row  = warp_m * 64 + (mat & 1) * 8 + lr;
    const int a_koff = (mat >> 1) * 16;   // bytes
    // B x4: matrices (n0-7,k0-7),(n0-7,k8-15),(n8-15,k0-7),(n8-15,k8-15)
    const int b_row  = warp_n * 32 + (mat >> 1) * 8 + lr;
    const int b_koff = (mat & 1) * 16;    // bytes

    // per-thread cp.async slots: 2 chunks of 16B per tile
    const int ld_r0 = tid >> 2;            // rows tid/4 and tid/4+64
    const int ld_c  = (tid & 3) * 16;      // byte col in 64B row
    const int ld_k  = (tid & 3) * 8;       // bf16 col

#define ISSUE_STAGE(s_)                                                        \
    do {                                                                       \
        const int k0_ = (s_) * KCH;                                            \
        const uint32_t st_ = sbase + ((s_) & 1) * STAGE_B;                     \
        const __nv_bfloat16* gsrc_[4] = {Ah, Al, Bh, Bl};                      \
        const int grow_[4] = {m0, m0, n0, n0};                                 \
        _Pragma("unroll")                                                      \
        for (int tI = 0; tI < 4; tI++) {                                       \
            _Pragma("unroll")                                                  \
            for (int i = 0; i < 2; i++) {                                      \
                int r_ = ld_r0 + i * 64;                                       \
                uint32_t dst_ = st_ + tI * TILE_B + r_ * ROW_STR + ld_c;       \
                const __nv_bfloat16* src_ =                                    \
                    gsrc_[tI] + (size_t)(grow_[tI] + r_) * D_ + k0_ + ld_k;    \
                CP_ASYNC16(dst_, src_);                                        \
            }                                                                  \
        }                                                                      \
        CP_COMMIT();                                                           \
    } while (0)

    ISSUE_STAGE(0);

    for (int s = 0; s < 32; s++) {
        if (s + 1 < 32) {
            ISSUE_STAGE(s + 1);
            asm volatile("cp.async.wait_group 1;" ::: "memory");
        } else {
            asm volatile("cp.async.wait_group 0;" ::: "memory");
        }
        __syncthreads();

        const uint32_t st = sbase + (s & 1) * STAGE_B;
#pragma unroll
        for (int ks = 0; ks < 2; ks++) {
            const uint32_t kb = ks * 32;  // 16 bf16 = 32B per k16 step
            uint32_t ah[4][4], al[4][4], bh[2][4], bl[2][4];
#pragma unroll
            for (int mt = 0; mt < 4; mt++) {
                uint32_t addr = st + (a_row + mt * 16) * ROW_STR + kb + a_koff;
                LDMATRIX_X4(ah[mt][0], ah[mt][1], ah[mt][2], ah[mt][3], addr);
                LDMATRIX_X4(al[mt][0], al[mt][1], al[mt][2], al[mt][3],
                            addr + TILE_B);
            }
#pragma unroll
            for (int pr = 0; pr < 2; pr++) {
                uint32_t addr = st + 2 * TILE_B +
                                (b_row + pr * 16) * ROW_STR + kb + b_koff;
                LDMATRIX_X4(bh[pr][0], bh[pr][1], bh[pr][2], bh[pr][3], addr);
                LDMATRIX_X4(bl[pr][0], bl[pr][1], bl[pr][2], bl[pr][3],
                            addr + TILE_B);
            }
#pragma unroll
            for (int mt = 0; mt < 4; mt++) {
#pragma unroll
                for (int nt = 0; nt < 4; nt++) {
                    const int p = nt >> 1, q = (nt & 1) * 2;
                    MMA_BF16(acc[mt][nt], ah[mt], bh[p][q], bh[p][q + 1]);
                    MMA_BF16(acc[mt][nt], ah[mt], bl[p][q], bl[p][q + 1]);
                    MMA_BF16(acc[mt][nt], al[mt], bh[p][q], bh[p][q + 1]);
                }
            }
        }
        __syncthreads();
    }

    // ------------------------------------------------------------------
    // Epilogue: optional RoPE, write C.
    // D frag: c0,c1 = (row = qr, cols qc, qc+1); c2,c3 = row qr+8.
    // qc is even -> RoPE (even,odd) pair lives in one thread.
    // ------------------------------------------------------------------
    const int qr = l >> 2;
    const int qc = (l & 3) * 2;
#pragma unroll
    for (int mt = 0; mt < 4; mt++) {
        const int r0 = m0 + warp_m * 64 + mt * 16 + qr;
        const int r1 = r0 + 8;
        const float *cb0 = 0, *sb0 = 0, *cb1 = 0, *sb1 = 0;
        if (rope) {
            int p0 = get_pos(tp32, r0 & (S_ - 1));
            int p1 = get_pos(tp32, r1 & (S_ - 1));
            cb0 = g_cos + p0 * (DK / 2); sb0 = g_sin + p0 * (DK / 2);
            cb1 = g_cos + p1 * (DK / 2); sb1 = g_sin + p1 * (DK / 2);
        }
#pragma unroll
        for (int nt = 0; nt < 4; nt++) {
            const int col = n0 + warp_n * 32 + nt * 8 + qc;
            float c0 = acc[mt][nt][0], c1 = acc[mt][nt][1];
            float c2 = acc[mt][nt][2], c3 = acc[mt][nt][3];
            if (rope) {
                const int pj = (col & (DK - 1)) >> 1;
                float cc = cb0[pj], ss = sb0[pj];
                float e = c0, o = c1;
                c0 = e * cc - o * ss; c1 = o * cc + e * ss;
                cc = cb1[pj]; ss = sb1[pj];
                e = c2; o = c3;
                c2 = e * cc - o * ss; c3 = o * cc + e * ss;
            }
            *(float2*)(C + (size_t)r0 * D_ + col) = make_float2(c0, c1);
            *(float2*)(C + (size_t)r1 * D_ + col) = make_float2(c2, c3);
        }
    }
}

// ---------------------------------------------------------------------------
// Flash attention, fp32, causal (unchanged from passing R3 kernel).
// ---------------------------------------------------------------------------
#define FA_SMEM ((3 * 64 * 65 + 64 * 64) * 4)

__global__ __launch_bounds__(128) void flash_kernel() {
    extern __shared__ float sm[];
    float* q_s = sm;
    float* k_s = sm + 64 * 65;
    float* p_s = sm + 2 * 64 * 65;
    float* v_s = sm + 3 * 64 * 65;

    const int tid = threadIdx.x;
    const int ty = tid >> 3;
    const int tx = tid & 7;
    const int qt = blockIdx.x;
    const int bh = blockIdx.y;
    const int b = bh >> 4;
    const int h = bh & 15;

    const float* qg = g_q + ((size_t)(b * S_) + qt * 64) * D_ + h * DK;
    for (int idx = tid; idx < 64 * 16; idx += 128) {
        int r = idx >> 4, c4 = idx & 15;
        float4 v = *(const float4*)(qg + (size_t)r * D_ + c4 * 4);
        float* dst = q_s + r * 65 + c4 * 4;
        dst[0] = v.x; dst[1] = v.y; dst[2] = v.z; dst[3] = v.w;
    }

    float m[4], l[4], acc[4][8];
#pragma unroll
    for (int i = 0; i < 4; i++) {
        m[i] = -INFINITY;
        l[i] = 0.f;
#pragma unroll
        for (int j = 0; j < 8; j++) acc[i][j] = 0.f;
    }

    for (int kt = 0; kt <= qt; kt++) {
        const float* kg = g_k + ((size_t)(b * S_) + kt * 64) * D_ + h * DK;
        const float* vg = g_v + ((size_t)(b * S_) + kt * 64) * D_ + h * DK;
        for (int idx = tid; idx < 64 * 16; idx += 128) {
            int r = idx >> 4, c4 = idx & 15;
            float4 kv = *(const float4*)(kg + (size_t)r * D_ + c4 * 4);
            float* kd = k_s + r * 65 + c4 * 4;
            kd[0] = kv.x; kd[1] = kv.y; kd[2] = kv.z; kd[3] = kv.w;
            float4 vv = *(const float4*)(vg + (size_t)r * D_ + c4 * 4);
            *(float4*)(v_s + r * 64 + c4 * 4) = vv;
        }
        __syncthreads();

        float sc[4][8];
#pragma unroll
        for (int i = 0; i < 4; i++)
#pragma unroll
            for (int j = 0; j < 8; j++) sc[i][j] = 0.f;

#pragma unroll 4
        for (int d = 0; d < 64; d++) {
            float a[4], bb[8];
#pragma unroll
            for (int i = 0; i < 4; i++) a[i] = q_s[(ty * 4 + i) * 65 + d];
#pragma unroll
            for (int j = 0; j < 8; j++) bb[j] = k_s[(tx * 8 + j) * 65 + d];
#pragma unroll
            for (int i = 0; i < 4; i++)
#pragma unroll
                for (int j = 0; j < 8; j++)
                    sc[i][j] += a[i] * bb[j];
        }

        const float scale = 0.125f;
        if (kt == qt) {
#pragma unroll
            for (int i = 0; i < 4; i++) {
                int rg = ty * 4 + i;
#pragma unroll
                for (int j = 0; j < 8; j++) {
                    int cg = tx * 8 + j;
                    sc[i][j] = (cg <= rg) ? sc[i][j] * scale : -INFINITY;
                }
            }
        } else {
#pragma unroll
            for (int i = 0; i < 4; i++)
#pragma unroll
                for (int j = 0; j < 8; j++) sc[i][j] *= scale;
        }

#pragma unroll
        for (int i = 0; i < 4; i++) {
            float tm = sc[i][0];
#pragma unroll
            for (int j = 1; j < 8; j++) tm = fmaxf(tm, sc[i][j]);
            tm = fmaxf(tm, __shfl_xor_sync(0xffffffffu, tm, 1));
            tm = fmaxf(tm, __shfl_xor_sync(0xffffffffu, tm, 2));
            tm = fmaxf(tm, __shfl_xor_sync(0xffffffffu, tm, 4));
            float newm = fmaxf(m[i], tm);
            float corr = __expf(m[i] - newm);
            float ps = 0.f;
#pragma unroll
            for (int j = 0; j < 8; j++) {
                float p = __expf(sc[i][j] - newm);
                p_s[(ty * 4 + i) * 65 + tx * 8 + j] = p;
                ps += p;
            }
            ps += __shfl_xor_sync(0xffffffffu, ps, 1);
            ps += __shfl_xor_sync(0xffffffffu, ps, 2);
            ps += __shfl_xor_sync(0xffffffffu, ps, 4);
            l[i] = l[i] * corr + ps;
            m[i] = newm;
#pragma unroll
            for (int j = 0; j < 8; j++) acc[i][j] *= corr;
        }
        __syncthreads();

#pragma unroll 4
        for (int k = 0; k < 64; k++) {
            float a[4];
#pragma unroll
            for (int i = 0; i < 4; i++) a[i] = p_s[(ty * 4 + i) * 65 + k];
            float4 b0 = *(const float4*)(v_s + k * 64 + tx * 8);
            float4 b1 = *(const float4*)(v_s + k * 64 + tx * 8 + 4);
            float bb[8] = {b0.x, b0.y, b0.z, b0.w, b1.x, b1.y, b1.z, b1.w};
#pragma unroll
            for (int i = 0; i < 4; i++)
#pragma unroll
                for (int j = 0; j < 8; j++)
                    acc[i][j] += a[i] * bb[j];
        }
        __syncthreads();
    }

    float* og = g_att + ((size_t)(b * S_) + qt * 64) * D_ + h * DK;
#pragma unroll
    for (int i = 0; i < 4; i++) {
        float inv = 1.f / l[i];
        int r = ty * 4 + i;
        float4 o0 = make_float4(acc[i][0] * inv, acc[i][1] * inv,
                                acc[i][2] * inv, acc[i][3] * inv);
        float4 o1 = make_float4(acc[i][4] * inv, acc[i][5] * inv,
                                acc[i][6] * inv, acc[i][7] * inv);
        *(float4*)(og + (size_t)r * D_ + tx * 8) = o0;
        *(float4*)(og + (size_t)r * D_ + tx * 8 + 4) = o1;
    }
}

// ---------------------------------------------------------------------------
// Launcher
// ---------------------------------------------------------------------------
extern "C" void kernel_launch(void* const* d_in, const int* in_sizes, int n_in,
                              void* d_out, int out_size)
{
    const float* x    = (const float*)d_in[0];
    const float* wq   = (const float*)d_in[1];
    const float* wk   = (const float*)d_in[2];
    const float* wv   = (const float*)d_in[3];
    const float* wo   = (const float*)d_in[4];
    const int*   tp32 = (const int*)d_in[5];
    (void)in_sizes; (void)n_in; (void)out_size;

    cudaFuncSetAttribute(flash_kernel,
                         cudaFuncAttributeMaxDynamicSharedMemorySize, FA_SMEM);
    cudaFuncSetAttribute(hmma_gemm_kernel,
                         cudaFuncAttributeMaxDynamicSharedMemorySize, GEMM_SMEM);

    void *pq, *pk, *pv, *pa;
    void *pxh, *pxl, *path, *patl;
    void *pwqh, *pwql, *pwkh, *pwkl, *pwvh, *pwvl, *pwoh, *pwol;
    cudaGetSymbolAddress(&pq, g_q);
    cudaGetSymbolAddress(&pk, g_k);
    cudaGetSymbolAddress(&pv, g_v);
    cudaGetSymbolAddress(&pa, g_att);
    cudaGetSymbolAddress(&pxh, g_xh);
    cudaGetSymbolAddress(&pxl, g_xl);
    cudaGetSymbolAddress(&path, g_ath);
    cudaGetSymbolAddress(&patl, g_atl);
    cudaGetSymbolAddress(&pwqh, g_wqh);
    cudaGetSymbolAddress(&pwql, g_wql);
    cudaGetSymbolAddress(&pwkh, g_wkh);
    cudaGetSymbolAddress(&pwkl, g_wkl);
    cudaGetSymbolAddress(&pwvh, g_wvh);
    cudaGetSymbolAddress(&pwvl, g_wvl);
    cudaGetSymbolAddress(&pwoh, g_woh);
    cudaGetSymbolAddress(&pwol, g_wol);

    // 1. RoPE tables
    rope_table_kernel<<<(MSEQ * (DK / 2) + 255) / 256, 256>>>();

    // 2. split x; transpose+split weights
    const int NX = M_ * D_;
    split_kernel<<<(NX + 255) / 256, 256>>>(x, (__nv_bfloat16*)pxh, (__nv_bfloat16*)pxl, NX);
    dim3 tb(32, 8), tg(32, 32);
    wsplit_kernel<<<tg, tb>>>(wq, (__nv_bfloat16*)pwqh, (__nv_bfloat16*)pwql);
    wsplit_kernel<<<tg, tb>>>(wk, (__nv_bfloat16*)pwkh, (__nv_bfloat16*)pwkl);
    wsplit_kernel<<<tg, tb>>>(wv, (__nv_bfloat16*)pwvh, (__nv_bfloat16*)pwvl);
    wsplit_kernel<<<tg, tb>>>(wo, (__nv_bfloat16*)pwoh, (__nv_bfloat16*)pwol);

    // 3. QKV projections via HMMA split-bf16 (RoPE fused for Q, K)
    dim3 gg(D_ / 128, M_ / 128);
    hmma_gemm_kernel<<<gg, 256, GEMM_SMEM>>>(
        (const __nv_bfloat16*)pxh, (const __nv_bfloat16*)pxl,
        (const __nv_bfloat16*)pwqh, (const __nv_bfloat16*)pwql,
        (float*)pq, tp32, 1);
    hmma_gemm_kernel<<<gg, 256, GEMM_SMEM>>>(
        (const __nv_bfloat16*)pxh, (const __nv_bfloat16*)pxl,
        (const __nv_bfloat16*)pwkh, (const __nv_bfloat16*)pwkl,
        (float*)pk, tp32, 1);
    hmma_gemm_kernel<<<gg, 256, GEMM_SMEM>>>(
        (const __nv_bfloat16*)pxh, (const __nv_bfloat16*)pxl,
        (const __nv_bfloat16*)pwvh, (const __nv_bfloat16*)pwvl,
        (float*)pv, tp32, 0);

    // 4. Causal flash attention (fp32)
    dim3 gf(S_ / 64, B_ * H_);
    flash_kernel<<<gf, 128, FA_SMEM>>>();

    // 5. split attention output, then o_proj via HMMA
    split_kernel<<<(NX + 255) / 256, 256>>>((const float*)pa,
                                            (__nv_bfloat16*)path, (__nv_bfloat16*)patl, NX);
    hmma_gemm_kernel<<<gg, 256, GEMM_SMEM>>>(
        (const __nv_bfloat16*)path, (const __nv_bfloat16*)patl,
        (const __nv_bfloat16*)pwoh, (const __nv_bfloat16*)pwol,
        (float*)d_out, tp32, 0);
}

// round 8
// speedup vs baseline: 3.0343x; 2.0302x over previous
#include <cuda_runtime.h>
#include <cuda_bf16.h>
#include <math.h>
#include <stdint.h>

// Problem constants
#define B_   4
#define S_   2048
#define D_   1024
#define H_   16
#define DK   64
#define MSEQ 2048
#define M_   (B_ * S_)   // 8192

// ---------------------------------------------------------------------------
// Scratch (__device__ globals; no allocations allowed)
// ---------------------------------------------------------------------------
__device__ float g_cos[MSEQ * (DK / 2)];
__device__ float g_sin[MSEQ * (DK / 2)];

// x and attention-out, split bf16, row-major [M_,1024]
__device__ __align__(16) __nv_bfloat16 g_xh[M_ * D_];
__device__ __align__(16) __nv_bfloat16 g_xl[M_ * D_];
__device__ __align__(16) __nv_bfloat16 g_ath[M_ * D_];
__device__ __align__(16) __nv_bfloat16 g_atl[M_ * D_];
// Q,K,V split bf16 in [b][h][s][d] layout
__device__ __align__(16) __nv_bfloat16 g_qbh[M_ * D_];
__device__ __align__(16) __nv_bfloat16 g_qbl[M_ * D_];
__device__ __align__(16) __nv_bfloat16 g_kbh[M_ * D_];
__device__ __align__(16) __nv_bfloat16 g_kbl[M_ * D_];
__device__ __align__(16) __nv_bfloat16 g_vbh[M_ * D_];
__device__ __align__(16) __nv_bfloat16 g_vbl[M_ * D_];
// transposed+split weights: [N=1024][K=1024] (k contiguous)
__device__ __align__(16) __nv_bfloat16 g_wqh[D_ * D_];
__device__ __align__(16) __nv_bfloat16 g_wql[D_ * D_];
__device__ __align__(16) __nv_bfloat16 g_wkh[D_ * D_];
__device__ __align__(16) __nv_bfloat16 g_wkl[D_ * D_];
__device__ __align__(16) __nv_bfloat16 g_wvh[D_ * D_];
__device__ __align__(16) __nv_bfloat16 g_wvl[D_ * D_];
__device__ __align__(16) __nv_bfloat16 g_woh[D_ * D_];
__device__ __align__(16) __nv_bfloat16 g_wol[D_ * D_];

// ---------------------------------------------------------------------------
// PTX helpers (sm_80+ only; harness compiles for plain sm_103 — no tcgen05)
// ---------------------------------------------------------------------------
__device__ __forceinline__ uint32_t smem_to_u32(const void* p) {
    uint32_t a;
    asm("{ .reg .u64 t; cvta.to.shared.u64 t, %1; cvt.u32.u64 %0, t; }"
        : "=r"(a) : "l"(p));
    return a;
}
#define CP_ASYNC16(dst_u32, src_ptr) \
    asm volatile("cp.async.cg.shared.global [%0], [%1], 16;" \
                 :: "r"(dst_u32), "l"(src_ptr))
#define CP_COMMIT() asm volatile("cp.async.commit_group;" ::: "memory")
#define CP_WAIT(n) asm volatile("cp.async.wait_group %0;" :: "n"(n) : "memory")
#define LDMATRIX_X4(r0, r1, r2, r3, addr) \
    asm volatile("ldmatrix.sync.aligned.m8n8.x4.shared.b16 {%0,%1,%2,%3}, [%4];" \
                 : "=r"(r0), "=r"(r1), "=r"(r2), "=r"(r3) : "r"(addr))
#define LDMATRIX_X4_T(r0, r1, r2, r3, addr) \
    asm volatile("ldmatrix.sync.aligned.m8n8.x4.trans.shared.b16 {%0,%1,%2,%3}, [%4];" \
                 : "=r"(r0), "=r"(r1), "=r"(r2), "=r"(r3) : "r"(addr))
#define MMA_BF16(c, a, b0, b1) \
    asm volatile("mma.sync.aligned.m16n8k16.row.col.f32.bf16.bf16.f32 " \
                 "{%0,%1,%2,%3}, {%4,%5,%6,%7}, {%8,%9}, {%0,%1,%2,%3};" \
                 : "+f"((c)[0]), "+f"((c)[1]), "+f"((c)[2]), "+f"((c)[3]) \
                 : "r"((a)[0]), "r"((a)[1]), "r"((a)[2]), "r"((a)[3]), \
                   "r"(b0), "r"(b1))

// pack two fp32 -> bf16x2 reg: low half = lo, high half = hi
__device__ __forceinline__ uint32_t pack_bf16x2(float lo, float hi) {
    uint32_t r;
    asm("cvt.rn.bf16x2.f32 %0, %1, %2;" : "=r"(r) : "f"(hi), "f"(lo));
    return r;
}
// hi/lo split of a pair, packed
__device__ __forceinline__ void split_pack(float v0, float v1,
                                           uint32_t& rh, uint32_t& rl) {
    rh = pack_bf16x2(v0, v1);
    float h0 = __uint_as_float(rh << 16);
    float h1 = __uint_as_float(rh & 0xffff0000u);
    rl = pack_bf16x2(v0 - h0, v1 - h1);
}

// fast exp2 on x<=0, FFMA-only (no MUFU). |err| ~ 2e-6 relative.
__device__ __forceinline__ float exp2f_fast(float x) {
    x = fmaxf(x, -120.f);
    float z = __fadd_rn(x, 12582912.f);            // round to nearest int
    int ei = __float_as_int(z) - 0x4B400000;       // integer part
    float f = x - __fadd_rn(z, -12582912.f);       // frac in [-0.5,0.5]
    float p = 0.0013333558f;
    p = fmaf(p, f, 0.0096181291f);
    p = fmaf(p, f, 0.0555041087f);
    p = fmaf(p, f, 0.2402265070f);
    p = fmaf(p, f, 0.69314718056f);
    p = fmaf(p, f, 1.0f);
    return __int_as_float(__float_as_int(p) + (ei << 23));
}

// token_positions dtype guard (int32 vs int64 little-endian)
__device__ __forceinline__ int get_pos(const int* __restrict__ tp32, int s) {
    return (tp32[1] == 0) ? tp32[2 * s] : tp32[s];
}

// ---------------------------------------------------------------------------
// split x (fp32 -> bf16 hi/lo) + RoPE tables folded in
// ---------------------------------------------------------------------------
__global__ void split_kernel(const float* __restrict__ in,
                             __nv_bfloat16* __restrict__ hi,
                             __nv_bfloat16* __restrict__ lo, int n)
{
    int i = blockIdx.x * blockDim.x + threadIdx.x;
    if (i < MSEQ * (DK / 2)) {
        int pos = i >> 5;
        int j   = i & 31;
        double freq = pow(10000.0, -(double)(2 * j) / (double)DK);
        double ang  = (double)pos * freq;
        g_cos[i] = (float)cos(ang);
        g_sin[i] = (float)sin(ang);
    }
    if (i < n) {
        float v = in[i];
        __nv_bfloat16 h = __float2bfloat16(v);
        hi[i] = h;
        lo[i] = __float2bfloat16(v - __bfloat162float(h));
    }
}

// ---------------------------------------------------------------------------
// Weight transpose + split: W[K][N] fp32 -> th/tl[N][K] bf16
// ---------------------------------------------------------------------------
__global__ void wsplit_kernel(const float* __restrict__ W,
                              __nv_bfloat16* __restrict__ th,
                              __nv_bfloat16* __restrict__ tl)
{
    __shared__ float t[32][33];
    int bx = blockIdx.x * 32;
    int by = blockIdx.y * 32;
    int tx = threadIdx.x, ty = threadIdx.y;
    for (int i = ty; i < 32; i += 8)
        t[i][tx] = W[(size_t)(by + i) * D_ + bx + tx];
    __syncthreads();
    for (int i = ty; i < 32; i += 8) {
        float v = t[tx][i];
        __nv_bfloat16 h = __float2bfloat16(v);
        size_t o = (size_t)(bx + i) * D_ + by + tx;
        th[o] = h;
        tl[o] = __float2bfloat16(v - __bfloat162float(h));
    }
}

// ---------------------------------------------------------------------------
// Shared HMMA GEMM core (proven in R5): acc[4][4][4] = A(128xK) @ B^T tile.
// ---------------------------------------------------------------------------
#define KCH      32
#define ROW_STR  80
#define TILE_B   (128 * ROW_STR)
#define STAGE_B  (4 * TILE_B)
#define GEMM_SMEM (2 * STAGE_B)

__device__ __forceinline__ void gemm_core(
    const __nv_bfloat16* __restrict__ Ah, const __nv_bfloat16* __restrict__ Al,
    const __nv_bfloat16* __restrict__ Bh, const __nv_bfloat16* __restrict__ Bl,
    int m0, int n0, char* smem, float acc[4][4][4])
{
    const uint32_t sbase = smem_to_u32(smem);
    const int tid = threadIdx.x;
    const int w = tid >> 5;
    const int l = tid & 31;
    const int warp_m = w >> 2;
    const int warp_n = w & 3;

    const int mat = l >> 3, lr = l & 7;
    const int a_row  = warp_m * 64 + (mat & 1) * 8 + lr;
    const int a_koff = (mat >> 1) * 16;
    const int b_row  = warp_n * 32 + (mat >> 1) * 8 + lr;
    const int b_koff = (mat & 1) * 16;

    const int ld_r0 = tid >> 2;
    const int ld_c  = (tid & 3) * 16;
    const int ld_k  = (tid & 3) * 8;

#define ISSUE_STAGE(s_)                                                        \
    do {                                                                       \
        const int k0_ = (s_) * KCH;                                            \
        const uint32_t st_ = sbase + ((s_) & 1) * STAGE_B;                     \
        const __nv_bfloat16* gsrc_[4] = {Ah, Al, Bh, Bl};                      \
        const int grow_[4] = {m0, m0, n0, n0};                                 \
        _Pragma("unroll")                                                      \
        for (int tI = 0; tI < 4; tI++) {                                       \
            _Pragma("unroll")                                                  \
            for (int i = 0; i < 2; i++) {                                      \
                int r_ = ld_r0 + i * 64;                                       \
                uint32_t dst_ = st_ + tI * TILE_B + r_ * ROW_STR + ld_c;       \
                const __nv_bfloat16* src_ =                                    \
                    gsrc_[tI] + (size_t)(grow_[tI] + r_) * D_ + k0_ + ld_k;    \
                CP_ASYNC16(dst_, src_);                                        \
            }                                                                  \
        }                                                                      \
        CP_COMMIT();                                                           \
    } while (0)

    ISSUE_STAGE(0);

    for (int s = 0; s < 32; s++) {
        if (s + 1 < 32) {
            ISSUE_STAGE(s + 1);
            CP_WAIT(1);
        } else {
            CP_WAIT(0);
        }
        __syncthreads();

        const uint32_t st = sbase + (s & 1) * STAGE_B;
#pragma unroll
        for (int ks = 0; ks < 2; ks++) {
            const uint32_t kb = ks * 32;
            uint32_t ah[4][4], al[4][4], bh[2][4], bl[2][4];
#pragma unroll
            for (int mt = 0; mt < 4; mt++) {
                uint32_t addr = st + (a_row + mt * 16) * ROW_STR + kb + a_koff;
                LDMATRIX_X4(ah[mt][0], ah[mt][1], ah[mt][2], ah[mt][3], addr);
                LDMATRIX_X4(al[mt][0], al[mt][1], al[mt][2], al[mt][3],
                            addr + TILE_B);
            }
#pragma unroll
            for (int pr = 0; pr < 2; pr++) {
                uint32_t addr = st + 2 * TILE_B +
                                (b_row + pr * 16) * ROW_STR + kb + b_koff;
                LDMATRIX_X4(bh[pr][0], bh[pr][1], bh[pr][2], bh[pr][3], addr);
                LDMATRIX_X4(bl[pr][0], bl[pr][1], bl[pr][2], bl[pr][3],
                            addr + TILE_B);
            }
#pragma unroll
            for (int mt = 0; mt < 4; mt++) {
#pragma unroll
                for (int nt = 0; nt < 4; nt++) {
                    const int p = nt >> 1, q = (nt & 1) * 2;
                    MMA_BF16(acc[mt][nt], ah[mt], bh[p][q], bh[p][q + 1]);
                    MMA_BF16(acc[mt][nt], ah[mt], bl[p][q], bl[p][q + 1]);
                    MMA_BF16(acc[mt][nt], al[mt], bh[p][q], bh[p][q + 1]);
                }
            }
        }
        __syncthreads();
    }
#undef ISSUE_STAGE
}

// ---------------------------------------------------------------------------
// Fused QKV projection: z=0 Q(+rope), z=1 K(+rope), z=2 V.
// Writes split bf16 into [b][h][s][d] layout.
// ---------------------------------------------------------------------------
__global__ __launch_bounds__(256) void hmma_qkv_kernel(const int* __restrict__ tp32)
{
    extern __shared__ char smem[];
    const int z = blockIdx.z;
    const __nv_bfloat16* Bh = (z == 0) ? g_wqh : (z == 1) ? g_wkh : g_wvh;
    const __nv_bfloat16* Bl = (z == 0) ? g_wql : (z == 1) ? g_wkl : g_wvl;
    __nv_bfloat16* Oh = (z == 0) ? g_qbh : (z == 1) ? g_kbh : g_vbh;
    __nv_bfloat16* Ol = (z == 0) ? g_qbl : (z == 1) ? g_kbl : g_vbl;
    const int rope = (z < 2);

    const int n0 = blockIdx.x * 128;
    const int m0 = blockIdx.y * 128;

    float acc[4][4][4];
#pragma unroll
    for (int mt = 0; mt < 4; mt++)
#pragma unroll
        for (int nt = 0; nt < 4; nt++)
#pragma unroll
            for (int r = 0; r < 4; r++) acc[mt][nt][r] = 0.f;

    gemm_core(g_xh, g_xl, Bh, Bl, m0, n0, smem, acc);

    const int w = threadIdx.x >> 5, l = threadIdx.x & 31;
    const int warp_m = w >> 2, warp_n = w & 3;
    const int qr = l >> 2, qc = (l & 3) * 2;

#pragma unroll
    for (int mt = 0; mt < 4; mt++) {
        const int r0 = m0 + warp_m * 64 + mt * 16 + qr;
        const int r1 = r0 + 8;
        const float *cb0 = 0, *sb0 = 0, *cb1 = 0, *sb1 = 0;
        if (rope) {
            int p0 = get_pos(tp32, r0 & (S_ - 1));
            int p1 = get_pos(tp32, r1 & (S_ - 1));
            cb0 = g_cos + p0 * (DK / 2); sb0 = g_sin + p0 * (DK / 2);
            cb1 = g_cos + p1 * (DK / 2); sb1 = g_sin + p1 * (DK / 2);
        }
        const int b0i = r0 >> 11, s0i = r0 & (S_ - 1);
        const int b1i = r1 >> 11, s1i = r1 & (S_ - 1);
#pragma unroll
        for (int nt = 0; nt < 4; nt++) {
            const int col = n0 + warp_n * 32 + nt * 8 + qc;
            const int h = col >> 6, d = col & 63;
            float c0 = acc[mt][nt][0], c1 = acc[mt][nt][1];
            float c2 = acc[mt][nt][2], c3 = acc[mt][nt][3];
            if (rope) {
                const int pj = d >> 1;
                float cc = cb0[pj], ss = sb0[pj];
                float e = c0, o = c1;
                c0 = e * cc - o * ss; c1 = o * cc + e * ss;
                cc = cb1[pj]; ss = sb1[pj];
                e = c2; o = c3;
                c2 = e * cc - o * ss; c3 = o * cc + e * ss;
            }
            uint32_t rh, rl;
            size_t i0 = (((size_t)(b0i * H_ + h) * S_ + s0i) * DK + d) >> 1;
            size_t i1 = (((size_t)(b1i * H_ + h) * S_ + s1i) * DK + d) >> 1;
            split_pack(c0, c1, rh, rl);
            ((uint32_t*)Oh)[i0] = rh; ((uint32_t*)Ol)[i0] = rl;
            split_pack(c2, c3, rh, rl);
            ((uint32_t*)Oh)[i1] = rh; ((uint32_t*)Ol)[i1] = rl;
        }
    }
}

// ---------------------------------------------------------------------------
// Output projection: fp32 out = att @ Wo
// ---------------------------------------------------------------------------
__global__ __launch_bounds__(256) void hmma_o_kernel(float* __restrict__ C)
{
    extern __shared__ char smem[];
    const int n0 = blockIdx.x * 128;
    const int m0 = blockIdx.y * 128;

    float acc[4][4][4];
#pragma unroll
    for (int mt = 0; mt < 4; mt++)
#pragma unroll
        for (int nt = 0; nt < 4; nt++)
#pragma unroll
            for (int r = 0; r < 4; r++) acc[mt][nt][r] = 0.f;

    gemm_core(g_ath, g_atl, g_woh, g_wol, m0, n0, smem, acc);

    const int w = threadIdx.x >> 5, l = threadIdx.x & 31;
    const int warp_m = w >> 2, warp_n = w & 3;
    const int qr = l >> 2, qc = (l & 3) * 2;
#pragma unroll
    for (int mt = 0; mt < 4; mt++) {
        const int r0 = m0 + warp_m * 64 + mt * 16 + qr;
        const int r1 = r0 + 8;
#pragma unroll
        for (int nt = 0; nt < 4; nt++) {
            const int col = n0 + warp_n * 32 + nt * 8 + qc;
            *(float2*)(C + (size_t)r0 * D_ + col) =
                make_float2(acc[mt][nt][0], acc[mt][nt][1]);
            *(float2*)(C + (size_t)r1 * D_ + col) =
                make_float2(acc[mt][nt][2], acc[mt][nt][3]);
        }
    }
}

// ---------------------------------------------------------------------------
// Flash attention, split-bf16 HMMA, causal.
// Block: 128 q-rows x (b,h). 8 warps x 16 rows. KV tiles of 64, double-buffered.
// ---------------------------------------------------------------------------
#define KV_STRIDE 144
#define KV_TILE   (64 * KV_STRIDE)       // 9216
#define FL_STAGE  (4 * KV_TILE)          // 36864: Kh, Kl, Vh, Vl
#define FL_SMEM   (2 * FL_STAGE)         // 73728
#define SCL 0.18033688011112042f         // 0.125 * log2(e)

__global__ __launch_bounds__(256) void flash_hmma_kernel()
{
    extern __shared__ char fs[];
    const uint32_t sbase = smem_to_u32(fs);
    const int tid = threadIdx.x;
    const int w = tid >> 5, l = tid & 31;
    const int qt = 15 - blockIdx.x;          // long blocks first
    const int bh = blockIdx.y;
    const int mat = l >> 3, lr = l & 7;
    const int qr = l >> 2, qc = (l & 3) * 2;

    const size_t bh_off = (size_t)bh * S_ * DK;
    const __nv_bfloat16* qh_g = g_qbh + bh_off + (size_t)qt * 128 * DK;
    const __nv_bfloat16* ql_g = g_qbl + bh_off + (size_t)qt * 128 * DK;
    const __nv_bfloat16* kh_g = g_kbh + bh_off;
    const __nv_bfloat16* kl_g = g_kbl + bh_off;
    const __nv_bfloat16* vh_g = g_vbh + bh_off;
    const __nv_bfloat16* vl_g = g_vbl + bh_off;

    // ---- load Q tile (128x64 hi + lo) into stage area, extract frags ----
    {
        const int r = tid >> 3, c = tid & 7;   // covers 256 of 1024 chunks/iter
#pragma unroll
        for (int t = 0; t < 2; t++) {
            const __nv_bfloat16* src = t ? ql_g : qh_g;
#pragma unroll
            for (int i = 0; i < 4; i++) {
                int p = tid + i * 256;
                int rr = p >> 3, cc = p & 7;
                CP_ASYNC16(sbase + t * 18432 + rr * KV_STRIDE + cc * 16,
                           src + (size_t)rr * DK + cc * 8);
            }
        }
        (void)r; (void)c;
        CP_COMMIT();
        CP_WAIT(0);
        __syncthreads();
    }
    uint32_t qhf[4][4], qlf[4][4];
#pragma unroll
    for (int ks = 0; ks < 4; ks++) {
        uint32_t addr = sbase + (w * 16 + (mat & 1) * 8 + lr) * KV_STRIDE +
                        ks * 32 + (mat >> 1) * 16;
        LDMATRIX_X4(qhf[ks][0], qhf[ks][1], qhf[ks][2], qhf[ks][3], addr);
        LDMATRIX_X4(qlf[ks][0], qlf[ks][1], qlf[ks][2], qlf[ks][3], addr + 18432);
    }
    __syncthreads();

    // ---- state ----
    float m0 = -1e30f, m1 = -1e30f, l0 = 0.f, l1 = 0.f;
    float ob[8][4];
#pragma unroll
    for (int j = 0; j < 8; j++)
#pragma unroll
        for (int r = 0; r < 4; r++) ob[j][r] = 0.f;

    const int r0g = qt * 128 + w * 16 + qr;
    const int r1g = r0g + 8;
    const int ktmax = 2 * qt + 1;

#define FL_ISSUE(kt_)                                                          \
    do {                                                                       \
        const uint32_t st_ = sbase + ((kt_) & 1) * FL_STAGE;                   \
        const __nv_bfloat16* gs_[4] = {kh_g, kl_g, vh_g, vl_g};                \
        _Pragma("unroll")                                                      \
        for (int t = 0; t < 4; t++) {                                          \
            _Pragma("unroll")                                                  \
            for (int i = 0; i < 2; i++) {                                      \
                int p = tid + i * 256;                                         \
                int rr = p >> 3, cc = p & 7;                                   \
                CP_ASYNC16(st_ + t * KV_TILE + rr * KV_STRIDE + cc * 16,       \
                           gs_[t] + (size_t)((kt_) * 64 + rr) * DK + cc * 8);  \
            }                                                                  \
        }                                                                      \
        CP_COMMIT();                                                           \
    } while (0)

    FL_ISSUE(0);

    for (int kt = 0; kt <= ktmax; kt++) {
        if (kt + 1 <= ktmax) { FL_ISSUE(kt + 1); CP_WAIT(1); }
        else                 { CP_WAIT(0); }
        __syncthreads();

        const uint32_t st = sbase + (kt & 1) * FL_STAGE;

        // ---- scores: S = Qh*Kh + Qh*Kl + Ql*Kh ----
        float sc[8][4];
#pragma unroll
        for (int j = 0; j < 8; j++)
#pragma unroll
            for (int r = 0; r < 4; r++) sc[j][r] = 0.f;

#pragma unroll
        for (int ks = 0; ks < 4; ks++) {
            uint32_t kh4[4][4], kl4[4][4];
#pragma unroll
            for (int t = 0; t < 4; t++) {
                uint32_t addr = st + (t * 16 + (mat >> 1) * 8 + lr) * KV_STRIDE +
                                ks * 32 + (mat & 1) * 16;
                LDMATRIX_X4(kh4[t][0], kh4[t][1], kh4[t][2], kh4[t][3], addr);
                LDMATRIX_X4(kl4[t][0], kl4[t][1], kl4[t][2], kl4[t][3],
                            addr + KV_TILE);
            }
#pragma unroll
            for (int j = 0; j < 8; j++) {
                const int t = j >> 1, q = (j & 1) * 2;
                MMA_BF16(sc[j], qhf[ks], kh4[t][q], kh4[t][q + 1]);
                MMA_BF16(sc[j], qhf[ks], kl4[t][q], kl4[t][q + 1]);
                MMA_BF16(sc[j], qlf[ks], kh4[t][q], kh4[t][q + 1]);
            }
        }

        // ---- scale + causal mask ----
#pragma unroll
        for (int j = 0; j < 8; j++)
#pragma unroll
            for (int r = 0; r < 4; r++) sc[j][r] *= SCL;
        if (kt >= 2 * qt) {
            const int cb = kt * 64;
#pragma unroll
            for (int j = 0; j < 8; j++) {
                int c0 = cb + j * 8 + qc, c1 = c0 + 1;
                if (c0 > r0g) sc[j][0] = -30000.f;
                if (c1 > r0g) sc[j][1] = -30000.f;
                if (c0 > r1g) sc[j][2] = -30000.f;
                if (c1 > r1g) sc[j][3] = -30000.f;
            }
        }

        // ---- online softmax (exp2 domain) ----
        float tm0 = -1e30f, tm1 = -1e30f;
#pragma unroll
        for (int j = 0; j < 8; j++) {
            tm0 = fmaxf(tm0, fmaxf(sc[j][0], sc[j][1]));
            tm1 = fmaxf(tm1, fmaxf(sc[j][2], sc[j][3]));
        }
        tm0 = fmaxf(tm0, __shfl_xor_sync(0xffffffffu, tm0, 1));
        tm0 = fmaxf(tm0, __shfl_xor_sync(0xffffffffu, tm0, 2));
        tm1 = fmaxf(tm1, __shfl_xor_sync(0xffffffffu, tm1, 1));
        tm1 = fmaxf(tm1, __shfl_xor_sync(0xffffffffu, tm1, 2));
        const float nm0 = fmaxf(m0, tm0), nm1 = fmaxf(m1, tm1);
        const float cor0 = exp2f_fast(m0 - nm0);
        const float cor1 = exp2f_fast(m1 - nm1);
        float s0 = 0.f, s1 = 0.f;
#pragma unroll
        for (int j = 0; j < 8; j++) {
            sc[j][0] = exp2f_fast(sc[j][0] - nm0);
            sc[j][1] = exp2f_fast(sc[j][1] - nm0);
            sc[j][2] = exp2f_fast(sc[j][2] - nm1);
            sc[j][3] = exp2f_fast(sc[j][3] - nm1);
            s0 += sc[j][0] + sc[j][1];
            s1 += sc[j][2] + sc[j][3];
        }
        s0 += __shfl_xor_sync(0xffffffffu, s0, 1);
        s0 += __shfl_xor_sync(0xffffffffu, s0, 2);
        s1 += __shfl_xor_sync(0xffffffffu, s1, 1);
        s1 += __shfl_xor_sync(0xffffffffu, s1, 2);
        l0 = l0 * cor0 + s0;
        l1 = l1 * cor1 + s1;
        m0 = nm0; m1 = nm1;
#pragma unroll
        for (int j = 0; j < 8; j++) {
            ob[j][0] *= cor0; ob[j][1] *= cor0;
            ob[j][2] *= cor1; ob[j][3] *= cor1;
        }

        // ---- PV: O += Ph*Vh + Ph*Vl + Pl*Vh ----
#pragma unroll
        for (int ks = 0; ks < 4; ks++) {
            uint32_t pah[4], pal[4];
            split_pack(sc[2 * ks][0], sc[2 * ks][1], pah[0], pal[0]);
            split_pack(sc[2 * ks][2], sc[2 * ks][3], pah[1], pal[1]);
            split_pack(sc[2 * ks + 1][0], sc[2 * ks + 1][1], pah[2], pal[2]);
            split_pack(sc[2 * ks + 1][2], sc[2 * ks + 1][3], pah[3], pal[3]);

            uint32_t vh4[4][4], vl4[4][4];
#pragma unroll
            for (int t = 0; t < 4; t++) {
                uint32_t addr = st + 2 * KV_TILE +
                                (ks * 16 + (mat & 1) * 8 + lr) * KV_STRIDE +
                                t * 32 + (mat >> 1) * 16;
                LDMATRIX_X4_T(vh4[t][0], vh4[t][1], vh4[t][2], vh4[t][3], addr);
                LDMATRIX_X4_T(vl4[t][0], vl4[t][1], vl4[t][2], vl4[t][3],
                              addr + KV_TILE);
            }
#pragma unroll
            for (int j = 0; j < 8; j++) {
                const int t = j >> 1, q = (j & 1) * 2;
                MMA_BF16(ob[j], pah, vh4[t][q], vh4[t][q + 1]);
                MMA_BF16(ob[j], pah, vl4[t][q], vl4[t][q + 1]);
                MMA_BF16(ob[j], pal, vh4[t][q], vh4[t][q + 1]);
            }
        }
        __syncthreads();
    }
#undef FL_ISSUE

    // ---- epilogue: normalize, split bf16, write row-major att layout ----
    const float inv0 = 1.f / l0, inv1 = 1.f / l1;
    const int b = bh >> 4, h = bh & 15;
    const size_t row0 = (size_t)b * S_ + r0g;   // r0g is in-batch seq index
    const size_t row1 = row0 + 8;
    uint32_t* oh32 = (uint32_t*)g_ath;
    uint32_t* ol32 = (uint32_t*)g_atl;
#pragma unroll
    for (int j = 0; j < 8; j++) {
        const int col = h * 64 + j * 8 + qc;
        uint32_t rh, rl;
        split_pack(ob[j][0] * inv0, ob[j][1] * inv0, rh, rl);
        oh32[(row0 * D_ + col) >> 1] = rh;
        ol32[(row0 * D_ + col) >> 1] = rl;
        split_pack(ob[j][2] * inv1, ob[j][3] * inv1, rh, rl);
        oh32[(row1 * D_ + col) >> 1] = rh;
        ol32[(row1 * D_ + col) >> 1] = rl;
    }
}

// ---------------------------------------------------------------------------
// Launcher. Order chosen so ncu (-s 5 -c 1) captures flash_hmma_kernel (#6).
// ---------------------------------------------------------------------------
extern "C" void kernel_launch(void* const* d_in, const int* in_sizes, int n_in,
                              void* d_out, int out_size)
{
    const float* x    = (const float*)d_in[0];
    const float* wq   = (const float*)d_in[1];
    const float* wk   = (const float*)d_in[2];
    const float* wv   = (const float*)d_in[3];
    const float* wo   = (const float*)d_in[4];
    const int*   tp32 = (const int*)d_in[5];
    (void)in_sizes; (void)n_in; (void)out_size;

    cudaFuncSetAttribute(hmma_qkv_kernel,
                         cudaFuncAttributeMaxDynamicSharedMemorySize, GEMM_SMEM);
    cudaFuncSetAttribute(hmma_o_kernel,
                         cudaFuncAttributeMaxDynamicSharedMemorySize, GEMM_SMEM);
    cudaFuncSetAttribute(flash_hmma_kernel,
                         cudaFuncAttributeMaxDynamicSharedMemorySize, FL_SMEM);

    void *pxh, *pxl;
    void *pwqh, *pwql, *pwkh, *pwkl, *pwvh, *pwvl, *pwoh, *pwol;
    cudaGetSymbolAddress(&pxh, g_xh);
    cudaGetSymbolAddress(&pxl, g_xl);
    cudaGetSymbolAddress(&pwqh, g_wqh);
    cudaGetSymbolAddress(&pwql, g_wql);
    cudaGetSymbolAddress(&pwkh, g_wkh);
    cudaGetSymbolAddress(&pwkl, g_wkl);
    cudaGetSymbolAddress(&pwvh, g_wvh);
    cudaGetSymbolAddress(&pwvl, g_wvl);
    cudaGetSymbolAddress(&pwoh, g_woh);
    cudaGetSymbolAddress(&pwol, g_wol);

    const int NX = M_ * D_;
    dim3 tb(32, 8), tg(32, 32);

    // 1. split x (+ RoPE tables)
    split_kernel<<<(NX + 255) / 256, 256>>>(x, (__nv_bfloat16*)pxh,
                                            (__nv_bfloat16*)pxl, NX);
    // 2-4. weight transpose+split (Q, K, V)
    wsplit_kernel<<<tg, tb>>>(wq, (__nv_bfloat16*)pwqh, (__nv_bfloat16*)pwql);
    wsplit_kernel<<<tg, tb>>>(wk, (__nv_bfloat16*)pwkh, (__nv_bfloat16*)pwkl);
    wsplit_kernel<<<tg, tb>>>(wv, (__nv_bfloat16*)pwvh, (__nv_bfloat16*)pwvl);

    // 5. fused QKV projections (RoPE fused for Q,K; split-bf16 BHSD out)
    dim3 gqkv(D_ / 128, M_ / 128, 3);
    hmma_qkv_kernel<<<gqkv, 256, GEMM_SMEM>>>(tp32);

    // 6. flash attention (tensorized) — ncu capture lands here
    dim3 gf(16, B_ * H_);
    flash_hmma_kernel<<<gf, 256, FL_SMEM>>>();

    // 7. Wo transpose+split
    wsplit_kernel<<<tg, tb>>>(wo, (__nv_bfloat16*)pwoh, (__nv_bfloat16*)pwol);

    // 8. output projection (fp32 to d_out)
    dim3 gg(D_ / 128, M_ / 128);
    hmma_o_kernel<<<gg, 256, GEMM_SMEM>>>((float*)d_out);
}